// round 3
// baseline (speedup 1.0000x reference)
#include <cuda_runtime.h>

#define TT   1024
#define FF   2048
#define LL   128
#define HH   256
#define GG   384
#define NF   14            // real features per CTA
#define NTH  512
#define NCTA 147           // ceil(2048/14)
#define PSTR 10            // pair-stride in u64 (8 pairs + 2 pad, keeps 16B alignment)

typedef unsigned long long u64;

// pre-duplicated (w,w) f32x2 weights, k-major (device scratch; no allocation)
__device__ u64 g_W1t[LL * HH];   // [k][j]  : dup(W1[j][k])
__device__ u64 g_W2t[HH * LL];   // [j][k'] : dup(W2[k'][j])
__device__ u64 g_Wht[LL * GG];   // [k][g]  : dup(Whh[g][k])

// shared-memory layout (u64 units)
#define OFF_HS   0
#define OFF_A1   (128 * PSTR)               // 1280
#define OFF_GH0  (OFF_A1 + 256 * PSTR)      // 3840
#define OFF_GH1  (OFF_GH0 + 384 * PSTR)     // 7680
#define OFF_BP0  (OFF_GH1 + 384 * PSTR)     // 11520
#define OFF_BP1  (OFF_BP0 + 128 * PSTR)     // 12800
#define U64_CNT  (OFF_BP1 + 128 * PSTR)     // 14080
#define FREG_CNT 1568
#define SMEM_BYTES (U64_CNT * 8 + FREG_CNT * 4)   // 118912 B

__device__ __forceinline__ u64 pk2(float lo, float hi) {
    u64 r; asm("mov.b64 %0, {%1, %2};" : "=l"(r) : "f"(lo), "f"(hi)); return r;
}
__device__ __forceinline__ float2 up2(u64 v) {
    float2 r; asm("mov.b64 {%0, %1}, %2;" : "=f"(r.x), "=f"(r.y) : "l"(v)); return r;
}
__device__ __forceinline__ u64 fma2(u64 a, u64 b, u64 c) {
    u64 d; asm("fma.rn.f32x2 %0, %1, %2, %3;" : "=l"(d) : "l"(a), "l"(b), "l"(c)); return d;
}
__device__ __forceinline__ u64 add2(u64 a, u64 b) {
    u64 d; asm("add.rn.f32x2 %0, %1, %2;" : "=l"(d) : "l"(a), "l"(b)); return d;
}
__device__ __forceinline__ float sigm(float x) { return 1.0f / (1.0f + expf(-x)); }

__global__ void prep_kernel(const float* __restrict__ W1,
                            const float* __restrict__ W2,
                            const float* __restrict__ Whh) {
    int i = blockIdx.x * blockDim.x + threadIdx.x;
    if (i < HH * LL) { int j = i / LL, k = i % LL; float w = W1[i]; g_W1t[k * HH + j] = pk2(w, w); }
    if (i < LL * HH) { int k = i / HH, j = i % HH; float w = W2[i]; g_W2t[j * LL + k] = pk2(w, w); }
    if (i < GG * LL) { int g = i / LL, k = i % LL; float w = Whh[i]; g_Wht[k * GG + g] = pk2(w, w); }
}

__global__ __launch_bounds__(NTH, 1)
void odernn_kernel(const float* __restrict__ times,
                   const float* __restrict__ vals,
                   const float* __restrict__ mask,
                   const float* __restrict__ b1,
                   const float* __restrict__ b2,
                   const float* __restrict__ Wih,
                   const float* __restrict__ bih,
                   const float* __restrict__ bhh,
                   float* __restrict__ out)
{
    extern __shared__ u64 sm[];
    float* fb   = (float*)(sm + U64_CNT);
    float* b1s  = fb;
    float* b2s  = fb + 256;
    float* bihs = fb + 384;
    float* wihs = fb + 768;
    float* bhhs = fb + 1152;
    float* xob  = fb + 1536;   // 16
    float* xms  = fb + 1552;   // 16

    const int tid = threadIdx.x;
    const int cta = blockIdx.x;

    for (int i = tid; i < 256; i += NTH) b1s[i] = b1[i];
    for (int i = tid; i < 128; i += NTH) b2s[i] = b2[i];
    for (int i = tid; i < 384; i += NTH) { bihs[i] = bih[i]; wihs[i] = Wih[i]; bhhs[i] = bhh[i]; }
    for (int i = tid; i < 128 * PSTR; i += NTH) sm[OFF_HS + i] = 0ull;   // h0 = 0
    __syncthreads();

    const int j2   = tid & 255;          // phase-A output column
    const int fp0A = (tid >> 8) * 4;     // phase-A feature-pair subset base {0,4}
    const int p    = tid & 127;
    const int g4   = tid >> 7;           // group 0..3
    const int halfB = g4 & 1;            // j-half (B) / k-half (C)
    const int fp0B  = (g4 >> 1) * 4;     // feature-pair subset base {0,4}

    for (int t = 0; t < TT; t++) {
        // per-step scalars: obs/mask for this CTA's features (reverse time)
        if (tid < 16) {
            int fg = cta * NF + tid;
            float xo = 0.0f, xm = 0.0f;
            if (tid < NF && fg < FF) {
                long it = (long)(TT - 1 - t) * FF + fg;
                xo = __ldg(vals + it);
                xm = __ldg(mask + it);
            }
            xob[tid] = xo; xms[tid] = xm;
        }
        float dt = 0.0f;
        if (t > 0) dt = __ldg(times + (TT - t)) - __ldg(times + (TT - 1 - t));

        // ---- Phase A: a1[f][j] = tanh(sum_k h[f][k] * W1[j][k] + b1[j])
        {
            u64 a0 = 0, a1 = 0, a2 = 0, a3 = 0;
            const u64* w = g_W1t + j2;
            #pragma unroll 4
            for (int k = 0; k < LL; k++) {
                u64 wv = __ldg(w + k * HH);
                const u64* hr = sm + OFF_HS + k * PSTR + fp0A;
                ulonglong2 h01 = *(const ulonglong2*)hr;
                ulonglong2 h23 = *(const ulonglong2*)(hr + 2);
                a0 = fma2(h01.x, wv, a0);
                a1 = fma2(h01.y, wv, a1);
                a2 = fma2(h23.x, wv, a2);
                a3 = fma2(h23.y, wv, a3);
            }
            float bb = b1s[j2];
            float2 v0 = up2(a0), v1 = up2(a1), v2 = up2(a2), v3 = up2(a3);
            ulonglong2 s01, s23;
            s01.x = pk2(tanhf(v0.x + bb), tanhf(v0.y + bb));
            s01.y = pk2(tanhf(v1.x + bb), tanhf(v1.y + bb));
            s23.x = pk2(tanhf(v2.x + bb), tanhf(v2.y + bb));
            s23.y = pk2(tanhf(v3.x + bb), tanhf(v3.y + bb));
            u64* ar = sm + OFF_A1 + j2 * PSTR + fp0A;
            *(ulonglong2*)ar       = s01;
            *(ulonglong2*)(ar + 2) = s23;
        }
        __syncthreads();

        // ---- Phase B: f_ode partials = sum_{j in half} A1[f][j] * W2[k'][j]
        {
            u64 a0 = 0, a1 = 0, a2 = 0, a3 = 0;
            const u64* w = g_W2t + p;
            const int j0 = halfB * 128;
            #pragma unroll 4
            for (int j = j0; j < j0 + 128; j++) {
                u64 wv = __ldg(w + j * LL);
                const u64* ar = sm + OFF_A1 + j * PSTR + fp0B;
                ulonglong2 v01 = *(const ulonglong2*)ar;
                ulonglong2 v23 = *(const ulonglong2*)(ar + 2);
                a0 = fma2(v01.x, wv, a0);
                a1 = fma2(v01.y, wv, a1);
                a2 = fma2(v23.x, wv, a2);
                a3 = fma2(v23.y, wv, a3);
            }
            u64* bp = sm + (halfB ? OFF_BP1 : OFF_BP0) + p * PSTR + fp0B;
            ulonglong2 s01; s01.x = a0; s01.y = a1;
            ulonglong2 s23; s23.x = a2; s23.y = a3;
            *(ulonglong2*)bp       = s01;
            *(ulonglong2*)(bp + 2) = s23;
        }
        __syncthreads();

        // ---- ODE update: h += dt * (B0 + B1 + b2)   (dt==0 at t==0 => no-op)
        {
            float bb = b2s[p];
            #pragma unroll
            for (int r = 0; r < 2; r++) {
                int fp = g4 + r * 4;
                float2 s  = up2(add2(sm[OFF_BP0 + p * PSTR + fp], sm[OFF_BP1 + p * PSTR + fp]));
                float2 hv = up2(sm[OFF_HS + p * PSTR + fp]);
                hv.x = fmaf(dt, s.x + bb, hv.x);
                hv.y = fmaf(dt, s.y + bb, hv.y);
                sm[OFF_HS + p * PSTR + fp] = pk2(hv.x, hv.y);
            }
        }
        __syncthreads();

        // ---- Phase C: gh partials = sum_{k in half} h[f][k] * Whh[g][k]
        {
            u64 ar0 = 0, ar1 = 0, ar2 = 0, ar3 = 0;   // gate r
            u64 az0 = 0, az1 = 0, az2 = 0, az3 = 0;   // gate z
            u64 an0 = 0, an1 = 0, an2 = 0, an3 = 0;   // gate n
            const int k0 = halfB * 64;
            #pragma unroll 2
            for (int k = k0; k < k0 + 64; k++) {
                const u64* wr = g_Wht + k * GG + p;
                u64 w0 = __ldg(wr), w1 = __ldg(wr + 128), w2v = __ldg(wr + 256);
                const u64* hr = sm + OFF_HS + k * PSTR + fp0B;
                ulonglong2 h01 = *(const ulonglong2*)hr;
                ulonglong2 h23 = *(const ulonglong2*)(hr + 2);
                ar0 = fma2(h01.x, w0, ar0);  az0 = fma2(h01.x, w1, az0);  an0 = fma2(h01.x, w2v, an0);
                ar1 = fma2(h01.y, w0, ar1);  az1 = fma2(h01.y, w1, az1);  an1 = fma2(h01.y, w2v, an1);
                ar2 = fma2(h23.x, w0, ar2);  az2 = fma2(h23.x, w1, az2);  an2 = fma2(h23.x, w2v, an2);
                ar3 = fma2(h23.y, w0, ar3);  az3 = fma2(h23.y, w1, az3);  an3 = fma2(h23.y, w2v, an3);
            }
            u64* gh = sm + (halfB ? OFF_GH1 : OFF_GH0);
            {
                u64* d = gh + p * PSTR + fp0B;
                ulonglong2 s01; s01.x = ar0; s01.y = ar1;
                ulonglong2 s23; s23.x = ar2; s23.y = ar3;
                *(ulonglong2*)d = s01; *(ulonglong2*)(d + 2) = s23;
            }
            {
                u64* d = gh + (p + 128) * PSTR + fp0B;
                ulonglong2 s01; s01.x = az0; s01.y = az1;
                ulonglong2 s23; s23.x = az2; s23.y = az3;
                *(ulonglong2*)d = s01; *(ulonglong2*)(d + 2) = s23;
            }
            {
                u64* d = gh + (p + 256) * PSTR + fp0B;
                ulonglong2 s01; s01.x = an0; s01.y = an1;
                ulonglong2 s23; s23.x = an2; s23.y = an3;
                *(ulonglong2*)d = s01; *(ulonglong2*)(d + 2) = s23;
            }
        }
        __syncthreads();

        // ---- GRU gates + mask update
        {
            float br = bhhs[p], bz = bhhs[p + 128], bn = bhhs[p + 256];
            float wir = wihs[p], wiz = wihs[p + 128], win = wihs[p + 256];
            float bir = bihs[p], biz = bihs[p + 128], binn = bihs[p + 256];
            #pragma unroll
            for (int r = 0; r < 2; r++) {
                int fp = g4 + r * 4;
                float2 ghr = up2(add2(sm[OFF_GH0 + p * PSTR + fp],         sm[OFF_GH1 + p * PSTR + fp]));
                float2 ghz = up2(add2(sm[OFF_GH0 + (p + 128) * PSTR + fp], sm[OFF_GH1 + (p + 128) * PSTR + fp]));
                float2 ghn = up2(add2(sm[OFF_GH0 + (p + 256) * PSTR + fp], sm[OFF_GH1 + (p + 256) * PSTR + fp]));
                float2 hv  = up2(sm[OFF_HS + p * PSTR + fp]);
                {
                    float x = xob[2 * fp], m = xms[2 * fp];
                    float rr = sigm(fmaf(x, wir, bir) + ghr.x + br);
                    float zz = sigm(fmaf(x, wiz, biz) + ghz.x + bz);
                    float nn = tanhf(fmaf(x, win, binn) + rr * (ghn.x + bn));
                    float hc = (1.0f - zz) * nn + zz * hv.x;
                    hv.x = m * hc + (1.0f - m) * hv.x;
                }
                {
                    float x = xob[2 * fp + 1], m = xms[2 * fp + 1];
                    float rr = sigm(fmaf(x, wir, bir) + ghr.y + br);
                    float zz = sigm(fmaf(x, wiz, biz) + ghz.y + bz);
                    float nn = tanhf(fmaf(x, win, binn) + rr * (ghn.y + bn));
                    float hc = (1.0f - zz) * nn + zz * hv.y;
                    hv.y = m * hc + (1.0f - m) * hv.y;
                }
                sm[OFF_HS + p * PSTR + fp] = pk2(hv.x, hv.y);
            }
        }
        __syncthreads();
    }

    // ---- store final h : out[f_global][k]
    const float* hf = (const float*)(sm + OFF_HS);   // float idx: k*(2*PSTR) + f
    for (int idx = tid; idx < NF * LL; idx += NTH) {
        int f = idx >> 7, k = idx & 127;
        int fg = cta * NF + f;
        if (fg < FF) out[fg * LL + k] = hf[k * 2 * PSTR + f];
    }
}

extern "C" void kernel_launch(void* const* d_in, const int* in_sizes, int n_in,
                              void* d_out, int out_size) {
    const float* times = (const float*)d_in[0];
    const float* vals  = (const float*)d_in[1];
    const float* mask  = (const float*)d_in[2];
    const float* W1    = (const float*)d_in[3];
    const float* b1    = (const float*)d_in[4];
    const float* W2    = (const float*)d_in[5];
    const float* b2    = (const float*)d_in[6];
    const float* Wih   = (const float*)d_in[7];
    const float* bih   = (const float*)d_in[8];
    const float* Whh   = (const float*)d_in[9];
    const float* bhh   = (const float*)d_in[10];
    float* out = (float*)d_out;

    (void)in_sizes; (void)n_in; (void)out_size;

    cudaFuncSetAttribute(odernn_kernel,
                         cudaFuncAttributeMaxDynamicSharedMemorySize, SMEM_BYTES);

    prep_kernel<<<(GG * LL + 255) / 256, 256>>>(W1, W2, Whh);
    odernn_kernel<<<NCTA, NTH, SMEM_BYTES>>>(times, vals, mask, b1, b2,
                                             Wih, bih, bhh, out);
}

// round 4
// speedup vs baseline: 1.0010x; 1.0010x over previous
#include <cuda_runtime.h>

#define TT   1024
#define FF   2048
#define LL   128
#define HH   256
#define GG   384
#define NF   16            // features per CTA (8 pairs, all real)
#define NTH  512
#define NCTA 128           // 2048 / 16
#define PSTR 10            // pair-stride in u64 (8 pairs + 2 pad, 16B-aligned rows)

typedef unsigned long long u64;

// plain f32 k-major transposed weights (device scratch; no allocation)
__device__ float g_W1t[LL * HH];   // [k][j]  = W1[j][k]
__device__ float g_W2t[HH * LL];   // [j][k'] = W2[k'][j]
__device__ float g_Wht[LL * GG];   // [k][g]  = Whh[g][k]

// shared-memory layout (u64 units)
#define OFF_HS   0                         // h: [k=128][PSTR]        -> 1280
#define OFF_A1   1280                      // A1: [j=256][PSTR]       -> 2560
#define OFF_SC   3840                      // scratch partials        -> 6912 (max: C)
#define U64_CNT  10752
#define FREG_CNT 1568
#define SMEM_BYTES (U64_CNT * 8 + FREG_CNT * 4)   // 92288 B

// partial strides (u64): per output-pair slot = 18 (16 data + 2 pad, 144B, 16B-aligned)
#define AP_BLK  2304     // A: [kh=2][jp=128][18]
#define BP_BLK  1152     // B: [jq=4][kp=64][18]
#define CP_BLK  3456     // C: [kh=2][gp=192][18]

__device__ __forceinline__ u64 pk2(float lo, float hi) {
    u64 r; asm("mov.b64 %0, {%1, %2};" : "=l"(r) : "f"(lo), "f"(hi)); return r;
}
__device__ __forceinline__ float2 up2(u64 v) {
    float2 r; asm("mov.b64 {%0, %1}, %2;" : "=f"(r.x), "=f"(r.y) : "l"(v)); return r;
}
__device__ __forceinline__ u64 fma2(u64 a, u64 b, u64 c) {
    u64 d; asm("fma.rn.f32x2 %0, %1, %2, %3;" : "=l"(d) : "l"(a), "l"(b), "l"(c)); return d;
}
__device__ __forceinline__ u64 add2(u64 a, u64 b) {
    u64 d; asm("add.rn.f32x2 %0, %1, %2;" : "=l"(d) : "l"(a), "l"(b)); return d;
}
__device__ __forceinline__ float sigm(float x) { return 1.0f / (1.0f + expf(-x)); }

__global__ void prep_kernel(const float* __restrict__ W1,
                            const float* __restrict__ W2,
                            const float* __restrict__ Whh) {
    int i = blockIdx.x * blockDim.x + threadIdx.x;
    if (i < HH * LL) { int j = i / LL, k = i % LL; g_W1t[k * HH + j] = W1[i]; }
    if (i < LL * HH) { int k = i / HH, j = i % HH; g_W2t[j * LL + k] = W2[i]; }
    if (i < GG * LL) { int g = i / LL, k = i % LL; g_Wht[k * GG + g] = Whh[i]; }
}

__global__ __launch_bounds__(NTH, 1)
void odernn_kernel(const float* __restrict__ times,
                   const float* __restrict__ vals,
                   const float* __restrict__ mask,
                   const float* __restrict__ b1,
                   const float* __restrict__ b2,
                   const float* __restrict__ Wih,
                   const float* __restrict__ bih,
                   const float* __restrict__ bhh,
                   float* __restrict__ out)
{
    extern __shared__ u64 sm[];
    float* fb   = (float*)(sm + U64_CNT);
    float* b1s  = fb;            // 256
    float* b2s  = fb + 256;      // 128
    float* bihs = fb + 384;      // 384
    float* wihs = fb + 768;      // 384
    float* bhhs = fb + 1152;     // 384
    float* xob  = fb + 1536;     // 16
    float* xms  = fb + 1552;     // 16

    const int tid = threadIdx.x;
    const int cta = blockIdx.x;

    for (int i = tid; i < 256; i += NTH) b1s[i] = b1[i];
    for (int i = tid; i < 128; i += NTH) b2s[i] = b2[i];
    for (int i = tid; i < 384; i += NTH) { bihs[i] = bih[i]; wihs[i] = Wih[i]; bhhs[i] = bhh[i]; }
    for (int i = tid; i < 128 * PSTR; i += NTH) sm[OFF_HS + i] = 0ull;   // h0 = 0
    __syncthreads();

    for (int t = 0; t < TT; t++) {
        // per-step scalars: obs/mask for this CTA's 16 features (reverse time)
        if (tid < NF) {
            long it = (long)(TT - 1 - t) * FF + (cta * NF + tid);
            xob[tid] = __ldg(vals + it);
            xms[tid] = __ldg(mask + it);
        }
        float dt = 0.0f;
        if (t > 0) dt = __ldg(times + (TT - t)) - __ldg(times + (TT - 1 - t));

        // ---- Phase A: partial a1[f][j] = sum_{k in half} h[f][k] * W1[j][k]
        if (tid < 256) {
            const int jp = tid & 127, kh = tid >> 7;
            u64 a0[8], a1v[8];
            #pragma unroll
            for (int i = 0; i < 8; i++) { a0[i] = 0ull; a1v[i] = 0ull; }
            const float* w = g_W1t + 2 * jp;
            const int k0 = kh * 64;
            #pragma unroll 2
            for (int k = k0; k < k0 + 64; k++) {
                float2 wv = __ldg((const float2*)(w + k * HH));
                u64 w0 = pk2(wv.x, wv.x), w1 = pk2(wv.y, wv.y);
                const u64* hr = sm + OFF_HS + k * PSTR;
                ulonglong2 hA = *(const ulonglong2*)hr;
                ulonglong2 hB = *(const ulonglong2*)(hr + 2);
                ulonglong2 hC = *(const ulonglong2*)(hr + 4);
                ulonglong2 hD = *(const ulonglong2*)(hr + 6);
                a0[0] = fma2(hA.x, w0, a0[0]);  a1v[0] = fma2(hA.x, w1, a1v[0]);
                a0[1] = fma2(hA.y, w0, a0[1]);  a1v[1] = fma2(hA.y, w1, a1v[1]);
                a0[2] = fma2(hB.x, w0, a0[2]);  a1v[2] = fma2(hB.x, w1, a1v[2]);
                a0[3] = fma2(hB.y, w0, a0[3]);  a1v[3] = fma2(hB.y, w1, a1v[3]);
                a0[4] = fma2(hC.x, w0, a0[4]);  a1v[4] = fma2(hC.x, w1, a1v[4]);
                a0[5] = fma2(hC.y, w0, a0[5]);  a1v[5] = fma2(hC.y, w1, a1v[5]);
                a0[6] = fma2(hD.x, w0, a0[6]);  a1v[6] = fma2(hD.x, w1, a1v[6]);
                a0[7] = fma2(hD.y, w0, a0[7]);  a1v[7] = fma2(hD.y, w1, a1v[7]);
            }
            u64* d = sm + OFF_SC + kh * AP_BLK + jp * 18;
            #pragma unroll
            for (int i = 0; i < 4; i++) {
                ulonglong2 s; s.x = a0[2*i]; s.y = a0[2*i+1];
                *(ulonglong2*)(d + 2*i) = s;
            }
            #pragma unroll
            for (int i = 0; i < 4; i++) {
                ulonglong2 s; s.x = a1v[2*i]; s.y = a1v[2*i+1];
                *(ulonglong2*)(d + 8 + 2*i) = s;
            }
        }
        __syncthreads();

        // ---- A-reduce + tanh -> A1[j][pair]
        {
            const int j = tid >> 1, ph = tid & 1;
            const u64* s0 = sm + OFF_SC + (j >> 1) * 18 + (j & 1) * 8 + ph * 4;
            ulonglong2 pA = *(const ulonglong2*)s0;
            ulonglong2 pB = *(const ulonglong2*)(s0 + 2);
            ulonglong2 qA = *(const ulonglong2*)(s0 + AP_BLK);
            ulonglong2 qB = *(const ulonglong2*)(s0 + AP_BLK + 2);
            u64 v0 = add2(pA.x, qA.x), v1 = add2(pA.y, qA.y);
            u64 v2 = add2(pB.x, qB.x), v3 = add2(pB.y, qB.y);
            float bb = b1s[j];
            float2 f0 = up2(v0), f1 = up2(v1), f2 = up2(v2), f3 = up2(v3);
            ulonglong2 o1, o2;
            o1.x = pk2(tanhf(f0.x + bb), tanhf(f0.y + bb));
            o1.y = pk2(tanhf(f1.x + bb), tanhf(f1.y + bb));
            o2.x = pk2(tanhf(f2.x + bb), tanhf(f2.y + bb));
            o2.y = pk2(tanhf(f3.x + bb), tanhf(f3.y + bb));
            u64* d = sm + OFF_A1 + j * PSTR + ph * 4;
            *(ulonglong2*)d       = o1;
            *(ulonglong2*)(d + 2) = o2;
        }
        __syncthreads();

        // ---- Phase B: partial f_ode[f][k'] = sum_{j in quarter} A1[f][j] * W2[k'][j]
        if (tid < 256) {
            const int kp = tid & 63, jq = tid >> 6;
            u64 a0[8], a1v[8];
            #pragma unroll
            for (int i = 0; i < 8; i++) { a0[i] = 0ull; a1v[i] = 0ull; }
            const float* w = g_W2t + 2 * kp;
            const int j0 = jq * 64;
            #pragma unroll 2
            for (int j = j0; j < j0 + 64; j++) {
                float2 wv = __ldg((const float2*)(w + j * LL));
                u64 w0 = pk2(wv.x, wv.x), w1 = pk2(wv.y, wv.y);
                const u64* ar = sm + OFF_A1 + j * PSTR;
                ulonglong2 hA = *(const ulonglong2*)ar;
                ulonglong2 hB = *(const ulonglong2*)(ar + 2);
                ulonglong2 hC = *(const ulonglong2*)(ar + 4);
                ulonglong2 hD = *(const ulonglong2*)(ar + 6);
                a0[0] = fma2(hA.x, w0, a0[0]);  a1v[0] = fma2(hA.x, w1, a1v[0]);
                a0[1] = fma2(hA.y, w0, a0[1]);  a1v[1] = fma2(hA.y, w1, a1v[1]);
                a0[2] = fma2(hB.x, w0, a0[2]);  a1v[2] = fma2(hB.x, w1, a1v[2]);
                a0[3] = fma2(hB.y, w0, a0[3]);  a1v[3] = fma2(hB.y, w1, a1v[3]);
                a0[4] = fma2(hC.x, w0, a0[4]);  a1v[4] = fma2(hC.x, w1, a1v[4]);
                a0[5] = fma2(hC.y, w0, a0[5]);  a1v[5] = fma2(hC.y, w1, a1v[5]);
                a0[6] = fma2(hD.x, w0, a0[6]);  a1v[6] = fma2(hD.x, w1, a1v[6]);
                a0[7] = fma2(hD.y, w0, a0[7]);  a1v[7] = fma2(hD.y, w1, a1v[7]);
            }
            u64* d = sm + OFF_SC + jq * BP_BLK + kp * 18;
            #pragma unroll
            for (int i = 0; i < 4; i++) {
                ulonglong2 s; s.x = a0[2*i]; s.y = a0[2*i+1];
                *(ulonglong2*)(d + 2*i) = s;
            }
            #pragma unroll
            for (int i = 0; i < 4; i++) {
                ulonglong2 s; s.x = a1v[2*i]; s.y = a1v[2*i+1];
                *(ulonglong2*)(d + 8 + 2*i) = s;
            }
        }
        __syncthreads();

        // ---- ODE update: h += dt * (sum of 4 B-partials + b2)
        if (tid < 256) {
            const int kk = tid >> 1, ph = tid & 1;
            const u64* bp = sm + OFF_SC + (kk >> 1) * 18 + (kk & 1) * 8 + ph * 4;
            ulonglong2 x0 = *(const ulonglong2*)bp;
            ulonglong2 x1 = *(const ulonglong2*)(bp + 2);
            ulonglong2 y0 = *(const ulonglong2*)(bp + BP_BLK);
            ulonglong2 y1 = *(const ulonglong2*)(bp + BP_BLK + 2);
            ulonglong2 z0 = *(const ulonglong2*)(bp + 2 * BP_BLK);
            ulonglong2 z1 = *(const ulonglong2*)(bp + 2 * BP_BLK + 2);
            ulonglong2 u0 = *(const ulonglong2*)(bp + 3 * BP_BLK);
            ulonglong2 u1 = *(const ulonglong2*)(bp + 3 * BP_BLK + 2);
            u64 s0 = add2(add2(x0.x, y0.x), add2(z0.x, u0.x));
            u64 s1 = add2(add2(x0.y, y0.y), add2(z0.y, u0.y));
            u64 s2 = add2(add2(x1.x, y1.x), add2(z1.x, u1.x));
            u64 s3 = add2(add2(x1.y, y1.y), add2(z1.y, u1.y));
            float bb = b2s[kk];
            u64* hp = sm + OFF_HS + kk * PSTR + ph * 4;
            ulonglong2 h01 = *(const ulonglong2*)hp;
            ulonglong2 h23 = *(const ulonglong2*)(hp + 2);
            float2 hv, sv;
            sv = up2(s0); hv = up2(h01.x);
            hv.x = fmaf(dt, sv.x + bb, hv.x); hv.y = fmaf(dt, sv.y + bb, hv.y);
            h01.x = pk2(hv.x, hv.y);
            sv = up2(s1); hv = up2(h01.y);
            hv.x = fmaf(dt, sv.x + bb, hv.x); hv.y = fmaf(dt, sv.y + bb, hv.y);
            h01.y = pk2(hv.x, hv.y);
            sv = up2(s2); hv = up2(h23.x);
            hv.x = fmaf(dt, sv.x + bb, hv.x); hv.y = fmaf(dt, sv.y + bb, hv.y);
            h23.x = pk2(hv.x, hv.y);
            sv = up2(s3); hv = up2(h23.y);
            hv.x = fmaf(dt, sv.x + bb, hv.x); hv.y = fmaf(dt, sv.y + bb, hv.y);
            h23.y = pk2(hv.x, hv.y);
            *(ulonglong2*)hp       = h01;
            *(ulonglong2*)(hp + 2) = h23;
        }
        __syncthreads();

        // ---- Phase C: partial gh[f][g] = sum_{k in half} h[f][k] * Whh[g][k]
        if (tid < 384) {
            const int kh = tid / 192;
            const int gp = tid - kh * 192;
            u64 a0[8], a1v[8];
            #pragma unroll
            for (int i = 0; i < 8; i++) { a0[i] = 0ull; a1v[i] = 0ull; }
            const float* w = g_Wht + 2 * gp;
            const int k0 = kh * 64;
            #pragma unroll 2
            for (int k = k0; k < k0 + 64; k++) {
                float2 wv = __ldg((const float2*)(w + k * GG));
                u64 w0 = pk2(wv.x, wv.x), w1 = pk2(wv.y, wv.y);
                const u64* hr = sm + OFF_HS + k * PSTR;
                ulonglong2 hA = *(const ulonglong2*)hr;
                ulonglong2 hB = *(const ulonglong2*)(hr + 2);
                ulonglong2 hC = *(const ulonglong2*)(hr + 4);
                ulonglong2 hD = *(const ulonglong2*)(hr + 6);
                a0[0] = fma2(hA.x, w0, a0[0]);  a1v[0] = fma2(hA.x, w1, a1v[0]);
                a0[1] = fma2(hA.y, w0, a0[1]);  a1v[1] = fma2(hA.y, w1, a1v[1]);
                a0[2] = fma2(hB.x, w0, a0[2]);  a1v[2] = fma2(hB.x, w1, a1v[2]);
                a0[3] = fma2(hB.y, w0, a0[3]);  a1v[3] = fma2(hB.y, w1, a1v[3]);
                a0[4] = fma2(hC.x, w0, a0[4]);  a1v[4] = fma2(hC.x, w1, a1v[4]);
                a0[5] = fma2(hC.y, w0, a0[5]);  a1v[5] = fma2(hC.y, w1, a1v[5]);
                a0[6] = fma2(hD.x, w0, a0[6]);  a1v[6] = fma2(hD.x, w1, a1v[6]);
                a0[7] = fma2(hD.y, w0, a0[7]);  a1v[7] = fma2(hD.y, w1, a1v[7]);
            }
            u64* d = sm + OFF_SC + kh * CP_BLK + gp * 18;
            #pragma unroll
            for (int i = 0; i < 4; i++) {
                ulonglong2 s; s.x = a0[2*i]; s.y = a0[2*i+1];
                *(ulonglong2*)(d + 2*i) = s;
            }
            #pragma unroll
            for (int i = 0; i < 4; i++) {
                ulonglong2 s; s.x = a1v[2*i]; s.y = a1v[2*i+1];
                *(ulonglong2*)(d + 8 + 2*i) = s;
            }
        }
        __syncthreads();

        // ---- GRU gates + mask update (reduces C partials inline)
        {
            #pragma unroll
            for (int it = 0; it < 2; it++) {
                const int idx = tid + it * NTH;
                const int p = idx & 127, fp = idx >> 7;
                const int orr = (p >> 1) * 18 + (p & 1) * 8 + fp;
                const int oz  = ((p + 128) >> 1) * 18 + (p & 1) * 8 + fp;
                const int on  = ((p + 256) >> 1) * 18 + (p & 1) * 8 + fp;
                float2 ghr = up2(add2(sm[OFF_SC + orr], sm[OFF_SC + CP_BLK + orr]));
                float2 ghz = up2(add2(sm[OFF_SC + oz ], sm[OFF_SC + CP_BLK + oz ]));
                float2 ghn = up2(add2(sm[OFF_SC + on ], sm[OFF_SC + CP_BLK + on ]));
                float br = bhhs[p], bz = bhhs[p + 128], bn = bhhs[p + 256];
                float wir = wihs[p], wiz = wihs[p + 128], win = wihs[p + 256];
                float bir = bihs[p], biz = bihs[p + 128], binn = bihs[p + 256];
                float2 hv = up2(sm[OFF_HS + p * PSTR + fp]);
                {
                    float x = xob[2 * fp], m = xms[2 * fp];
                    float rr = sigm(fmaf(x, wir, bir) + ghr.x + br);
                    float zz = sigm(fmaf(x, wiz, biz) + ghz.x + bz);
                    float nn = tanhf(fmaf(x, win, binn) + rr * (ghn.x + bn));
                    float hc = (1.0f - zz) * nn + zz * hv.x;
                    hv.x = m * hc + (1.0f - m) * hv.x;
                }
                {
                    float x = xob[2 * fp + 1], m = xms[2 * fp + 1];
                    float rr = sigm(fmaf(x, wir, bir) + ghr.y + br);
                    float zz = sigm(fmaf(x, wiz, biz) + ghz.y + bz);
                    float nn = tanhf(fmaf(x, win, binn) + rr * (ghn.y + bn));
                    float hc = (1.0f - zz) * nn + zz * hv.y;
                    hv.y = m * hc + (1.0f - m) * hv.y;
                }
                sm[OFF_HS + p * PSTR + fp] = pk2(hv.x, hv.y);
            }
        }
        __syncthreads();
    }

    // ---- store final h : out[f_global][k]
    const float* hf = (const float*)(sm + OFF_HS);   // float idx: k*(2*PSTR) + f
    for (int idx = tid; idx < NF * LL; idx += NTH) {
        int f = idx >> 7, k = idx & 127;
        out[(cta * NF + f) * LL + k] = hf[k * 2 * PSTR + f];
    }
}

extern "C" void kernel_launch(void* const* d_in, const int* in_sizes, int n_in,
                              void* d_out, int out_size) {
    const float* times = (const float*)d_in[0];
    const float* vals  = (const float*)d_in[1];
    const float* mask  = (const float*)d_in[2];
    const float* W1    = (const float*)d_in[3];
    const float* b1    = (const float*)d_in[4];
    const float* W2    = (const float*)d_in[5];
    const float* b2    = (const float*)d_in[6];
    const float* Wih   = (const float*)d_in[7];
    const float* bih   = (const float*)d_in[8];
    const float* Whh   = (const float*)d_in[9];
    const float* bhh   = (const float*)d_in[10];
    float* out = (float*)d_out;

    (void)in_sizes; (void)n_in; (void)out_size;

    cudaFuncSetAttribute(odernn_kernel,
                         cudaFuncAttributeMaxDynamicSharedMemorySize, SMEM_BYTES);

    prep_kernel<<<(GG * LL + 255) / 256, 256>>>(W1, W2, Whh);
    odernn_kernel<<<NCTA, NTH, SMEM_BYTES>>>(times, vals, mask, b1, b2,
                                             Wih, bih, bhh, out);
}

// round 6
// speedup vs baseline: 1.8032x; 1.8015x over previous
#include <cuda_runtime.h>

#define TT   1024
#define FF   2048
#define LL   128
#define HH   256
#define GG   384
#define NF   16            // features per CTA (8 pairs)
#define NTH  256
#define NCTA 128           // 2048 / 16
#define PSTR 10            // pair-stride in u64 (8 pairs + 2 pad)

typedef unsigned long long u64;

// k-major transposed weights, padded for prefetch-ring overrun (no allocation)
__device__ float g_W1t[LL * HH + 2048];   // [k][j]  = W1[j][k]
__device__ float g_W2t[HH * LL + 2048];   // [j][k'] = W2[k'][j]
__device__ float g_Wht[LL * GG + 2048];   // [k][g]  = Whh[g][k]

// shared-memory layout (u64 units)
#define OFF_HS   0                          // h: [k=128][10]   -> 1280
#define OFF_A1   1280                       // A1: [j=256][10]  -> 2560
#define OFF_SC   3840                       // partial scratch
#define AP_BLK   2304                       // A: [kh=2][jp=128][18]
#define BP_BLK   1152                       // B: [jq=4][kp=64][18]
#define CP_BLK   3840                       // C: [kh=2][p=128][gate=3][10]
#define U64_CNT  11520
#define SMEM_BYTES (U64_CNT * 8 + 64 * 4)   // 92416 B

__device__ __forceinline__ u64 pk2(float lo, float hi) {
    u64 r; asm("mov.b64 %0, {%1, %2};" : "=l"(r) : "f"(lo), "f"(hi)); return r;
}
__device__ __forceinline__ float2 up2(u64 v) {
    float2 r; asm("mov.b64 {%0, %1}, %2;" : "=f"(r.x), "=f"(r.y) : "l"(v)); return r;
}
__device__ __forceinline__ u64 fma2(u64 a, u64 b, u64 c) {
    u64 d; asm("fma.rn.f32x2 %0, %1, %2, %3;" : "=l"(d) : "l"(a), "l"(b), "l"(c)); return d;
}
__device__ __forceinline__ u64 add2(u64 a, u64 b) {
    u64 d; asm("add.rn.f32x2 %0, %1, %2;" : "=l"(d) : "l"(a), "l"(b)); return d;
}
__device__ __forceinline__ float sigm(float x) { return 1.0f / (1.0f + expf(-x)); }

__global__ void prep_kernel(const float* __restrict__ W1,
                            const float* __restrict__ W2,
                            const float* __restrict__ Whh) {
    int i = blockIdx.x * blockDim.x + threadIdx.x;
    if (i < HH * LL) { int j = i / LL, k = i % LL; g_W1t[k * HH + j] = W1[i]; }
    if (i < LL * HH) { int k = i / HH, j = i % HH; g_W2t[j * LL + k] = W2[i]; }
    if (i < GG * LL) { int g = i / LL, k = i % LL; g_Wht[k * GG + g] = Whh[i]; }
}

__global__ __launch_bounds__(NTH, 1)
void odernn_kernel(const float* __restrict__ times,
                   const float* __restrict__ vals,
                   const float* __restrict__ mask,
                   const float* __restrict__ b1,
                   const float* __restrict__ b2,
                   const float* __restrict__ Wih,
                   const float* __restrict__ bih,
                   const float* __restrict__ bhh,
                   float* __restrict__ out)
{
    extern __shared__ u64 sm[];
    float* xob = (float*)(sm + U64_CNT);     // 16
    float* xms = (float*)(sm + U64_CNT) + 16;

    const int tid = threadIdx.x;
    const int cta = blockIdx.x;

    for (int i = tid; i < 128 * PSTR; i += NTH) sm[OFF_HS + i] = 0ull;   // h0 = 0

    // thread-resident constants
    const int jp  = tid & 127;           // phase-A j-pair
    const int kh  = tid >> 7;            // k-half (phases A, C)
    const int kp  = tid & 63;            // phase-B k'-pair
    const int jq  = tid >> 6;            // phase-B j-quarter
    const int p   = tid & 127;           // latent index (C / GRU)
    const int fh  = tid >> 7;            // GRU feature-half
    const float bbA = __ldg(b1 + tid);                    // A-reduce bias
    const float bbO = __ldg(b2 + (tid >> 1));             // ODE bias
    const float brg = __ldg(bhh + p), bzg = __ldg(bhh + p + 128), bng = __ldg(bhh + p + 256);
    const float wir = __ldg(Wih + p), wiz = __ldg(Wih + p + 128), win = __ldg(Wih + p + 256);
    const float bir = __ldg(bih + p), biz = __ldg(bih + p + 128), binn = __ldg(bih + p + 256);
    __syncthreads();

    for (int t = 0; t < TT; t++) {
        if (tid < NF) {
            long it = (long)(TT - 1 - t) * FF + (cta * NF + tid);
            xob[tid] = __ldg(vals + it);
            xms[tid] = __ldg(mask + it);
        }
        float dt = 0.0f;
        if (t > 0) dt = __ldg(times + (TT - t)) - __ldg(times + (TT - 1 - t));

        // ---- Phase A: partial a1[f][2jp..] = sum_{k in half} h[f][k]*W1t[k][2jp..]
        {
            const int k0 = kh * 64;
            const float2* w = (const float2*)g_W1t + jp;   // stride 128 float2 per k
            float2 buf[8];
            #pragma unroll
            for (int u = 0; u < 8; u++) buf[u] = __ldg(w + (k0 + u) * 128);
            u64 a0[8], a1v[8];
            #pragma unroll
            for (int i = 0; i < 8; i++) { a0[i] = 0ull; a1v[i] = 0ull; }
            for (int kk = 0; kk < 64; kk += 8) {
                #pragma unroll
                for (int u = 0; u < 8; u++) {
                    float2 wv = buf[u];
                    buf[u] = __ldg(w + (k0 + kk + u + 8) * 128);   // ring prefetch (padded)
                    u64 w0 = pk2(wv.x, wv.x), w1 = pk2(wv.y, wv.y);
                    const u64* hr = sm + OFF_HS + (k0 + kk + u) * PSTR;
                    ulonglong2 hA = *(const ulonglong2*)hr;
                    ulonglong2 hB = *(const ulonglong2*)(hr + 2);
                    ulonglong2 hC = *(const ulonglong2*)(hr + 4);
                    ulonglong2 hD = *(const ulonglong2*)(hr + 6);
                    a0[0] = fma2(hA.x, w0, a0[0]);  a1v[0] = fma2(hA.x, w1, a1v[0]);
                    a0[1] = fma2(hA.y, w0, a0[1]);  a1v[1] = fma2(hA.y, w1, a1v[1]);
                    a0[2] = fma2(hB.x, w0, a0[2]);  a1v[2] = fma2(hB.x, w1, a1v[2]);
                    a0[3] = fma2(hB.y, w0, a0[3]);  a1v[3] = fma2(hB.y, w1, a1v[3]);
                    a0[4] = fma2(hC.x, w0, a0[4]);  a1v[4] = fma2(hC.x, w1, a1v[4]);
                    a0[5] = fma2(hC.y, w0, a0[5]);  a1v[5] = fma2(hC.y, w1, a1v[5]);
                    a0[6] = fma2(hD.x, w0, a0[6]);  a1v[6] = fma2(hD.x, w1, a1v[6]);
                    a0[7] = fma2(hD.y, w0, a0[7]);  a1v[7] = fma2(hD.y, w1, a1v[7]);
                }
            }
            u64* d = sm + OFF_SC + kh * AP_BLK + jp * 18;
            #pragma unroll
            for (int i = 0; i < 4; i++) {
                ulonglong2 s; s.x = a0[2*i]; s.y = a0[2*i+1];
                *(ulonglong2*)(d + 2*i) = s;
            }
            #pragma unroll
            for (int i = 0; i < 4; i++) {
                ulonglong2 s; s.x = a1v[2*i]; s.y = a1v[2*i+1];
                *(ulonglong2*)(d + 8 + 2*i) = s;
            }
        }
        __syncthreads();

        // ---- A-reduce + tanh -> A1[j][8 pairs]   (j = tid)
        {
            const u64* s0 = sm + OFF_SC + (tid >> 1) * 18 + (tid & 1) * 8;
            ulonglong2 pA = *(const ulonglong2*)s0;
            ulonglong2 pB = *(const ulonglong2*)(s0 + 2);
            ulonglong2 pC = *(const ulonglong2*)(s0 + 4);
            ulonglong2 pD = *(const ulonglong2*)(s0 + 6);
            ulonglong2 qA = *(const ulonglong2*)(s0 + AP_BLK);
            ulonglong2 qB = *(const ulonglong2*)(s0 + AP_BLK + 2);
            ulonglong2 qC = *(const ulonglong2*)(s0 + AP_BLK + 4);
            ulonglong2 qD = *(const ulonglong2*)(s0 + AP_BLK + 6);
            float2 f0 = up2(add2(pA.x, qA.x)), f1 = up2(add2(pA.y, qA.y));
            float2 f2 = up2(add2(pB.x, qB.x)), f3 = up2(add2(pB.y, qB.y));
            float2 f4 = up2(add2(pC.x, qC.x)), f5 = up2(add2(pC.y, qC.y));
            float2 f6 = up2(add2(pD.x, qD.x)), f7 = up2(add2(pD.y, qD.y));
            ulonglong2 o0, o1, o2, o3;
            o0.x = pk2(tanhf(f0.x + bbA), tanhf(f0.y + bbA));
            o0.y = pk2(tanhf(f1.x + bbA), tanhf(f1.y + bbA));
            o1.x = pk2(tanhf(f2.x + bbA), tanhf(f2.y + bbA));
            o1.y = pk2(tanhf(f3.x + bbA), tanhf(f3.y + bbA));
            o2.x = pk2(tanhf(f4.x + bbA), tanhf(f4.y + bbA));
            o2.y = pk2(tanhf(f5.x + bbA), tanhf(f5.y + bbA));
            o3.x = pk2(tanhf(f6.x + bbA), tanhf(f6.y + bbA));
            o3.y = pk2(tanhf(f7.x + bbA), tanhf(f7.y + bbA));
            u64* d = sm + OFF_A1 + tid * PSTR;
            *(ulonglong2*)d       = o0;
            *(ulonglong2*)(d + 2) = o1;
            *(ulonglong2*)(d + 4) = o2;
            *(ulonglong2*)(d + 6) = o3;
        }
        __syncthreads();

        // ---- Phase B: partial f_ode[f][2kp..] = sum_{j in quarter} A1[f][j]*W2t[j][2kp..]
        {
            const int j0 = jq * 64;
            const float2* w = (const float2*)g_W2t + kp;   // stride 64 float2 per j
            float2 buf[8];
            #pragma unroll
            for (int u = 0; u < 8; u++) buf[u] = __ldg(w + (j0 + u) * 64);
            u64 a0[8], a1v[8];
            #pragma unroll
            for (int i = 0; i < 8; i++) { a0[i] = 0ull; a1v[i] = 0ull; }
            for (int jj = 0; jj < 64; jj += 8) {
                #pragma unroll
                for (int u = 0; u < 8; u++) {
                    float2 wv = buf[u];
                    buf[u] = __ldg(w + (j0 + jj + u + 8) * 64);    // ring prefetch (padded)
                    u64 w0 = pk2(wv.x, wv.x), w1 = pk2(wv.y, wv.y);
                    const u64* ar = sm + OFF_A1 + (j0 + jj + u) * PSTR;
                    ulonglong2 hA = *(const ulonglong2*)ar;
                    ulonglong2 hB = *(const ulonglong2*)(ar + 2);
                    ulonglong2 hC = *(const ulonglong2*)(ar + 4);
                    ulonglong2 hD = *(const ulonglong2*)(ar + 6);
                    a0[0] = fma2(hA.x, w0, a0[0]);  a1v[0] = fma2(hA.x, w1, a1v[0]);
                    a0[1] = fma2(hA.y, w0, a0[1]);  a1v[1] = fma2(hA.y, w1, a1v[1]);
                    a0[2] = fma2(hB.x, w0, a0[2]);  a1v[2] = fma2(hB.x, w1, a1v[2]);
                    a0[3] = fma2(hB.y, w0, a0[3]);  a1v[3] = fma2(hB.y, w1, a1v[3]);
                    a0[4] = fma2(hC.x, w0, a0[4]);  a1v[4] = fma2(hC.x, w1, a1v[4]);
                    a0[5] = fma2(hC.y, w0, a0[5]);  a1v[5] = fma2(hC.y, w1, a1v[5]);
                    a0[6] = fma2(hD.x, w0, a0[6]);  a1v[6] = fma2(hD.x, w1, a1v[6]);
                    a0[7] = fma2(hD.y, w0, a0[7]);  a1v[7] = fma2(hD.y, w1, a1v[7]);
                }
            }
            u64* d = sm + OFF_SC + jq * BP_BLK + kp * 18;
            #pragma unroll
            for (int i = 0; i < 4; i++) {
                ulonglong2 s; s.x = a0[2*i]; s.y = a0[2*i+1];
                *(ulonglong2*)(d + 2*i) = s;
            }
            #pragma unroll
            for (int i = 0; i < 4; i++) {
                ulonglong2 s; s.x = a1v[2*i]; s.y = a1v[2*i+1];
                *(ulonglong2*)(d + 8 + 2*i) = s;
            }
        }
        __syncthreads();

        // ---- ODE update: h += dt * (sum of 4 B-partials + b2)
        {
            const int kk = tid >> 1, ph = tid & 1;
            const u64* bp = sm + OFF_SC + (kk >> 1) * 18 + (kk & 1) * 8 + ph * 4;
            ulonglong2 x0 = *(const ulonglong2*)bp;
            ulonglong2 x1 = *(const ulonglong2*)(bp + 2);
            ulonglong2 y0 = *(const ulonglong2*)(bp + BP_BLK);
            ulonglong2 y1 = *(const ulonglong2*)(bp + BP_BLK + 2);
            ulonglong2 z0 = *(const ulonglong2*)(bp + 2 * BP_BLK);
            ulonglong2 z1 = *(const ulonglong2*)(bp + 2 * BP_BLK + 2);
            ulonglong2 u0 = *(const ulonglong2*)(bp + 3 * BP_BLK);
            ulonglong2 u1 = *(const ulonglong2*)(bp + 3 * BP_BLK + 2);
            u64 s0 = add2(add2(x0.x, y0.x), add2(z0.x, u0.x));
            u64 s1 = add2(add2(x0.y, y0.y), add2(z0.y, u0.y));
            u64 s2 = add2(add2(x1.x, y1.x), add2(z1.x, u1.x));
            u64 s3 = add2(add2(x1.y, y1.y), add2(z1.y, u1.y));
            u64* hp = sm + OFF_HS + kk * PSTR + ph * 4;
            ulonglong2 h01 = *(const ulonglong2*)hp;
            ulonglong2 h23 = *(const ulonglong2*)(hp + 2);
            float2 hv, sv;
            sv = up2(s0); hv = up2(h01.x);
            hv.x = fmaf(dt, sv.x + bbO, hv.x); hv.y = fmaf(dt, sv.y + bbO, hv.y);
            h01.x = pk2(hv.x, hv.y);
            sv = up2(s1); hv = up2(h01.y);
            hv.x = fmaf(dt, sv.x + bbO, hv.x); hv.y = fmaf(dt, sv.y + bbO, hv.y);
            h01.y = pk2(hv.x, hv.y);
            sv = up2(s2); hv = up2(h23.x);
            hv.x = fmaf(dt, sv.x + bbO, hv.x); hv.y = fmaf(dt, sv.y + bbO, hv.y);
            h23.x = pk2(hv.x, hv.y);
            sv = up2(s3); hv = up2(h23.y);
            hv.x = fmaf(dt, sv.x + bbO, hv.x); hv.y = fmaf(dt, sv.y + bbO, hv.y);
            h23.y = pk2(hv.x, hv.y);
            *(ulonglong2*)hp       = h01;
            *(ulonglong2*)(hp + 2) = h23;
        }
        __syncthreads();

        // ---- Phase C: partial gh[f][g] for g = p, p+128, p+256 over k-half
        {
            const int k0 = kh * 64;
            const float* w = g_Wht + p;
            float br0[4], br1[4], br2[4];
            #pragma unroll
            for (int u = 0; u < 4; u++) {
                const float* wr = w + (k0 + u) * GG;
                br0[u] = __ldg(wr); br1[u] = __ldg(wr + 128); br2[u] = __ldg(wr + 256);
            }
            u64 ar[8], az[8], an[8];
            #pragma unroll
            for (int i = 0; i < 8; i++) { ar[i] = 0ull; az[i] = 0ull; an[i] = 0ull; }
            for (int kk2 = 0; kk2 < 64; kk2 += 4) {
                #pragma unroll
                for (int u = 0; u < 4; u++) {
                    float w0f = br0[u], w1f = br1[u], w2f = br2[u];
                    const float* wr = w + (k0 + kk2 + u + 4) * GG;   // ring prefetch (padded)
                    br0[u] = __ldg(wr); br1[u] = __ldg(wr + 128); br2[u] = __ldg(wr + 256);
                    u64 w0 = pk2(w0f, w0f), w1 = pk2(w1f, w1f), w2 = pk2(w2f, w2f);
                    const u64* hr = sm + OFF_HS + (k0 + kk2 + u) * PSTR;
                    ulonglong2 hA = *(const ulonglong2*)hr;
                    ulonglong2 hB = *(const ulonglong2*)(hr + 2);
                    ulonglong2 hC = *(const ulonglong2*)(hr + 4);
                    ulonglong2 hD = *(const ulonglong2*)(hr + 6);
                    ar[0] = fma2(hA.x, w0, ar[0]); az[0] = fma2(hA.x, w1, az[0]); an[0] = fma2(hA.x, w2, an[0]);
                    ar[1] = fma2(hA.y, w0, ar[1]); az[1] = fma2(hA.y, w1, az[1]); an[1] = fma2(hA.y, w2, an[1]);
                    ar[2] = fma2(hB.x, w0, ar[2]); az[2] = fma2(hB.x, w1, az[2]); an[2] = fma2(hB.x, w2, an[2]);
                    ar[3] = fma2(hB.y, w0, ar[3]); az[3] = fma2(hB.y, w1, az[3]); an[3] = fma2(hB.y, w2, an[3]);
                    ar[4] = fma2(hC.x, w0, ar[4]); az[4] = fma2(hC.x, w1, az[4]); an[4] = fma2(hC.x, w2, an[4]);
                    ar[5] = fma2(hC.y, w0, ar[5]); az[5] = fma2(hC.y, w1, az[5]); an[5] = fma2(hC.y, w2, an[5]);
                    ar[6] = fma2(hD.x, w0, ar[6]); az[6] = fma2(hD.x, w1, az[6]); an[6] = fma2(hD.x, w2, an[6]);
                    ar[7] = fma2(hD.y, w0, ar[7]); az[7] = fma2(hD.y, w1, az[7]); an[7] = fma2(hD.y, w2, an[7]);
                }
            }
            u64* d = sm + OFF_SC + kh * CP_BLK + p * 30;
            #pragma unroll
            for (int i = 0; i < 4; i++) {
                ulonglong2 s; s.x = ar[2*i]; s.y = ar[2*i+1];
                *(ulonglong2*)(d + 2*i) = s;
            }
            #pragma unroll
            for (int i = 0; i < 4; i++) {
                ulonglong2 s; s.x = az[2*i]; s.y = az[2*i+1];
                *(ulonglong2*)(d + 10 + 2*i) = s;
            }
            #pragma unroll
            for (int i = 0; i < 4; i++) {
                ulonglong2 s; s.x = an[2*i]; s.y = an[2*i+1];
                *(ulonglong2*)(d + 20 + 2*i) = s;
            }
        }
        __syncthreads();

        // ---- GRU gates + mask update (reduces C partials inline)
        {
            const int b0 = OFF_SC + p * 30;
            #pragma unroll
            for (int q = 0; q < 4; q++) {
                const int fp = fh * 4 + q;
                float2 ghr = up2(add2(sm[b0 + fp],      sm[b0 + CP_BLK + fp]));
                float2 ghz = up2(add2(sm[b0 + 10 + fp], sm[b0 + CP_BLK + 10 + fp]));
                float2 ghn = up2(add2(sm[b0 + 20 + fp], sm[b0 + CP_BLK + 20 + fp]));
                float2 hv  = up2(sm[OFF_HS + p * PSTR + fp]);
                {
                    float x = xob[2 * fp], m = xms[2 * fp];
                    float rr = sigm(fmaf(x, wir, bir) + ghr.x + brg);
                    float zz = sigm(fmaf(x, wiz, biz) + ghz.x + bzg);
                    float nn = tanhf(fmaf(x, win, binn) + rr * (ghn.x + bng));
                    float hc = (1.0f - zz) * nn + zz * hv.x;
                    hv.x = m * hc + (1.0f - m) * hv.x;
                }
                {
                    float x = xob[2 * fp + 1], m = xms[2 * fp + 1];
                    float rr = sigm(fmaf(x, wir, bir) + ghr.y + brg);
                    float zz = sigm(fmaf(x, wiz, biz) + ghz.y + bzg);
                    float nn = tanhf(fmaf(x, win, binn) + rr * (ghn.y + bng));
                    float hc = (1.0f - zz) * nn + zz * hv.y;
                    hv.y = m * hc + (1.0f - m) * hv.y;
                }
                sm[OFF_HS + p * PSTR + fp] = pk2(hv.x, hv.y);
            }
        }
        __syncthreads();
    }

    // ---- store final h : out[f_global][k]
    const float* hf = (const float*)(sm + OFF_HS);   // float idx: k*(2*PSTR) + f
    for (int idx = tid; idx < NF * LL; idx += NTH) {
        int f = idx >> 7, k = idx & 127;
        out[(cta * NF + f) * LL + k] = hf[k * 2 * PSTR + f];
    }
}

extern "C" void kernel_launch(void* const* d_in, const int* in_sizes, int n_in,
                              void* d_out, int out_size) {
    const float* times = (const float*)d_in[0];
    const float* vals  = (const float*)d_in[1];
    const float* mask  = (const float*)d_in[2];
    const float* W1    = (const float*)d_in[3];
    const float* b1    = (const float*)d_in[4];
    const float* W2    = (const float*)d_in[5];
    const float* b2    = (const float*)d_in[6];
    const float* Wih   = (const float*)d_in[7];
    const float* bih   = (const float*)d_in[8];
    const float* Whh   = (const float*)d_in[9];
    const float* bhh   = (const float*)d_in[10];
    float* out = (float*)d_out;

    (void)in_sizes; (void)n_in; (void)out_size;

    cudaFuncSetAttribute(odernn_kernel,
                         cudaFuncAttributeMaxDynamicSharedMemorySize, SMEM_BYTES);

    prep_kernel<<<(GG * LL + 255) / 256, 256>>>(W1, W2, Whh);
    odernn_kernel<<<NCTA, NTH, SMEM_BYTES>>>(times, vals, mask, b1, b2,
                                             Wih, bih, bhh, out);
}